// round 13
// baseline (speedup 1.0000x reference)
#include <cuda_runtime.h>
#include <cuda_fp16.h>
#include <cstdint>
#include <math.h>

// Problem constants
#define BB   1024
#define LL   2048
#define DEC  64
#define HH   128
#define GG   512         // 4*H gate rows
#define EINF 18          // encoder input features (16 emb + cont*w + x)
#define NKT  10          // k-tiles of 16 (k 0..159; 146..159 zero pad)
#define BT   8           // batch rows per CTA (= mma N)
#define NCTA (BB/BT)     // 128
#define NTHR 512         // 16 warps -> 4 per SMSP (latency hiding)
#define NW   16
#define XST  200         // xhT row stride in fp16 (conflict-free B-frag banks)
#define FPW  20          // W fragments per warp: 2 mtiles x 10 ktiles
#define NFRAG (NW * FPW * 32)   // 10240

// ---------------- persistent device scratch ----------------
__device__ uint4 g_Whf_e[NFRAG];   // enc W fp16, mma-fragment order (rows permuted)
__device__ uint4 g_Whf_d[NFRAG];   // dec
__device__ float g_fe[(size_t)BB * LL * EINF];
__device__ float g_fd[BB * DEC * 17];

// ---------------- smem byte layout ----------------
#define XH0_OFF   0                         // 3200 B : xh^T fp16 [8][200] buf 0
#define XH1_OFF   3200                      // 3200 B : buf 1
#define HBUF_OFF  6400                      // 4096 B : h fp32 [128][8] (decoder)
#define HW_OFF    10496                     // 3096 B : head weights/biases
#define SMEM_TOTAL 13592

// ---------------- mma wrapper ----------------
__device__ __forceinline__ void mma_f16(float* d, const uint4& a,
                                        uint32_t b0, uint32_t b1) {
    asm volatile(
        "mma.sync.aligned.m16n8k16.row.col.f32.f16.f16.f32 "
        "{%0,%1,%2,%3}, {%4,%5,%6,%7}, {%8,%9}, {%0,%1,%2,%3};"
        : "+f"(d[0]), "+f"(d[1]), "+f"(d[2]), "+f"(d[3])
        : "r"(a.x), "r"(a.y), "r"(a.z), "r"(a.w), "r"(b0), "r"(b1));
}

// ---------------- fast activations (HW tanh, fp32) ----------------
__device__ __forceinline__ float th(float x) {
    float y;
    asm("tanh.approx.f32 %0, %1;" : "=f"(y) : "f"(x));
    return y;
}
__device__ __forceinline__ float sg(float x) {
    return fmaf(0.5f, th(0.5f * x), 0.5f);
}

// ---------------- prep kernels ----------------
__device__ __forceinline__ float getW(const float* Wih, const float* Whh,
                                      int R, int k) {
    if (k < 18)  return Wih[R * 18 + k];
    if (k < 146) return Whh[R * 128 + (k - 18)];
    return 0.0f;
}
__device__ __forceinline__ uint32_t packh2(float a, float b) {
    __half2 h = __floats2half2_rn(a, b);   // low = a
    return *reinterpret_cast<uint32_t*>(&h);
}

// Permutation for 16 warps x 2 mtiles: warp w, mtile mt, mma row (g | g+8) ->
// gate (2*mt + s) of element e = w*8 + g, i.e. gate row R = (2*mt+s)*128 + e.
// Thread (w,lane) accumulators: dA = {i,f} x cols {c0,c0+1}, dB = {g,o} x cols.
__global__ void prep_Wfrag(const float* __restrict__ Wih,
                           const float* __restrict__ Whh,
                           uint4* __restrict__ w_out) {
    int idx = blockIdx.x * blockDim.x + threadIdx.x;
    if (idx >= NFRAG) return;
    int frag = idx >> 5, lane = idx & 31;
    int w = frag / FPW, rem = frag - w * FPW;
    int mt = rem / NKT, kt = rem - mt * NKT;
    int g = lane >> 2, t4 = lane & 3;
    int e = w * 8 + g;
    int R0 = (2 * mt + 0) * 128 + e;   // s=0 (mma row g)
    int R1 = (2 * mt + 1) * 128 + e;   // s=1 (mma row g+8)
    int kc = kt * 16 + 2 * t4;
    float v[8];
    v[0] = getW(Wih, Whh, R0, kc);     v[1] = getW(Wih, Whh, R0, kc + 1);
    v[2] = getW(Wih, Whh, R1, kc);     v[3] = getW(Wih, Whh, R1, kc + 1);
    v[4] = getW(Wih, Whh, R0, kc + 8); v[5] = getW(Wih, Whh, R0, kc + 9);
    v[6] = getW(Wih, Whh, R1, kc + 8); v[7] = getW(Wih, Whh, R1, kc + 9);
    w_out[idx] = make_uint4(packh2(v[0], v[1]), packh2(v[2], v[3]),
                            packh2(v[4], v[5]), packh2(v[6], v[7]));
}

__global__ void prep_fe(const int* __restrict__ cat, const float* __restrict__ cont,
                        const float* __restrict__ X, const float* __restrict__ emb,
                        const float* __restrict__ cw, float* __restrict__ out) {
    size_t idx = (size_t)blockIdx.x * blockDim.x + threadIdx.x;
    if (idx >= (size_t)BB * LL * EINF) return;
    size_t bl = idx / EINF;
    int j = (int)(idx - bl * EINF);
    float v;
    if (j < 16)       v = emb[cat[bl] * 16 + j];
    else if (j == 16) v = cont[bl] * cw[0];
    else              v = X[bl];
    out[idx] = v;
}

__global__ void prep_fd(const int* __restrict__ cat, const float* __restrict__ cont,
                        const float* __restrict__ emb, const float* __restrict__ cw,
                        float* __restrict__ out) {
    int idx = blockIdx.x * blockDim.x + threadIdx.x;
    if (idx >= BB * DEC * 17) return;
    int bl = idx / 17, j = idx - bl * 17;
    out[idx] = (j < 16) ? emb[cat[bl] * 16 + j] : cont[bl] * cw[0];
}

// ---------------- main persistent kernel ----------------
__global__ void __launch_bounds__(NTHR, 1)
model_kernel(const float* __restrict__ b_e, const float* __restrict__ b_d,
             const float* __restrict__ Wm, const float* __restrict__ bm,
             const float* __restrict__ Wsw, const float* __restrict__ bs,
             const float* __restrict__ Wv, const float* __restrict__ bv,
             float* __restrict__ out) {
    extern __shared__ char smem[];
    __half* xbuf[2] = { reinterpret_cast<__half*>(smem + XH0_OFF),
                        reinterpret_cast<__half*>(smem + XH1_OFF) };
    float*  hbuf = reinterpret_cast<float*>(smem + HBUF_OFF);
    float*  hw   = reinterpret_cast<float*>(smem + HW_OFF);

    const int tid = threadIdx.x;
    const int b0r = blockIdx.x * BT;
    const int w = tid >> 5, lane = tid & 31;
    const int g = lane >> 2, t4 = lane & 3;
    const int e  = w * 8 + g;             // this thread's cell element
    const int c0 = 2 * t4;                // this thread's 2 batch cols: c0, c0+1

    // ---- load encoder W into registers (20 frags = 80 regs) ----
    uint4 Wh[FPW];
    {
        const uint4* src = g_Whf_e + (size_t)w * FPW * 32 + lane;
#pragma unroll
        for (int i = 0; i < FPW; ++i) Wh[i] = src[i * 32];
    }
    // biases for element e
    float bi = b_e[e], bf = b_e[128 + e], bg = b_e[256 + e], bo = b_e[384 + e];

    // zero both xh buffers (h0 = 0; K padding stays 0 forever)
    for (int i = tid; i < (2 * BT * XST) / 2; i += NTHR)
        reinterpret_cast<uint32_t*>(xbuf[0])[i] = 0;

    // head weights
    if (tid < 128) {
        hw[tid]       = Wm[tid];
        hw[128 + tid] = Wsw[tid];
#pragma unroll
        for (int d = 0; d < 4; ++d) hw[256 + d * 128 + tid] = Wv[d * 128 + tid];
    }
    if (tid == 0) {
        hw[768] = bm[0]; hw[769] = bs[0];
        hw[770] = bv[0]; hw[771] = bv[1]; hw[772] = bv[2]; hw[773] = bv[3];
    }
    __syncthreads();
    // initial x features (t=0) -> buffer 0
    if (tid < BT * EINF) {
        int pr = tid / EINF, pk = tid - pr * EINF;
        xbuf[0][pr * XST + pk] =
            __float2half(g_fe[(size_t)(b0r + pr) * (LL * EINF) + pk]);
    }

    float c[2] = {0.f, 0.f};   // states: (e,c0), (e,c0+1)

#pragma unroll 1
    for (int t = 0; t < LL + DEC; ++t) {
        if (t == LL) {
            const uint4* src = g_Whf_d + (size_t)w * FPW * 32 + lane;
#pragma unroll
            for (int i = 0; i < FPW; ++i) Wh[i] = src[i * 32];
            bi = b_d[e]; bf = b_d[128 + e]; bg = b_d[256 + e]; bo = b_d[384 + e];
        }
        const __half* cur = xbuf[t & 1];
        __half*       nxt = xbuf[(t + 1) & 1];
        __syncthreads();                      // cur complete (h + features)

        // ---- ISSUE feature prefetch LDG early; MMA phase hides its latency ----
        float pf = 0.0f; bool havepf = false; int pr = 0, pk = 0;
        if (t < LL - 1) {
            if (tid < BT * EINF) {
                havepf = true; pr = tid / EINF; pk = tid - pr * EINF;
                pf = g_fe[(size_t)(b0r + pr) * (LL * EINF) + (size_t)(t + 1) * EINF + pk];
            }
        } else if (t >= LL && t < LL + DEC - 1) {
            int td = t - LL;
            if (tid < BT * 17) {
                havepf = true; pr = tid / 17; pk = tid - pr * 17;
                pf = g_fd[((b0r + pr) * DEC + td) * 17 + pk];
            }
        }

        // ---- gate GEMM: 4 chains of depth 5 (halved dependency latency) ----
        const __half* xp = cur + g * XST;
        float dA0[4], dB0[4], dA1[4], dB1[4];
        dA0[0] = bi; dA0[1] = bi; dA0[2] = bf; dA0[3] = bf;
        dB0[0] = bg; dB0[1] = bg; dB0[2] = bo; dB0[3] = bo;
#pragma unroll
        for (int q = 0; q < 4; ++q) { dA1[q] = 0.f; dB1[q] = 0.f; }
#pragma unroll
        for (int kt = 0; kt < 5; ++kt) {
            uint32_t a0 = *reinterpret_cast<const uint32_t*>(xp + kt * 16 + 2 * t4);
            uint32_t a1 = *reinterpret_cast<const uint32_t*>(xp + kt * 16 + 2 * t4 + 8);
            uint32_t e0 = *reinterpret_cast<const uint32_t*>(xp + (kt + 5) * 16 + 2 * t4);
            uint32_t e1 = *reinterpret_cast<const uint32_t*>(xp + (kt + 5) * 16 + 2 * t4 + 8);
            mma_f16(dA0, Wh[kt],           a0, a1);
            mma_f16(dB0, Wh[NKT + kt],     a0, a1);
            mma_f16(dA1, Wh[kt + 5],       e0, e1);
            mma_f16(dB1, Wh[NKT + kt + 5], e0, e1);
        }

        // ---- LSTM cell: fully in registers, fp32 (2 states/thread) ----
        float gi0 = dA0[0] + dA1[0], gi1 = dA0[1] + dA1[1];
        float gf0 = dA0[2] + dA1[2], gf1 = dA0[3] + dA1[3];
        float gg0 = dB0[0] + dB1[0], gg1 = dB0[1] + dB1[1];
        float go0 = dB0[2] + dB1[2], go1 = dB0[3] + dB1[3];
        c[0] = sg(gf0) * c[0] + sg(gi0) * th(gg0);
        c[1] = sg(gf1) * c[1] + sg(gi1) * th(gg1);
        float h0 = sg(go0) * th(c[0]);
        float h1 = sg(go1) * th(c[1]);
        nxt[c0 * XST + 18 + e]       = __float2half(h0);
        nxt[(c0 + 1) * XST + 18 + e] = __float2half(h1);

        // ---- store prefetched features / seam copy ----
        if (havepf) {
            nxt[pr * XST + pk] = __float2half(pf);
        } else if (t == LL - 1) {
            // decoder t0 reuses encoder's last features (f_prev, x_prev)
            if (tid < BT * EINF) {
                int qr = tid / EINF, qk = tid - qr * EINF;
                nxt[qr * XST + qk] = cur[qr * XST + qk];
            }
        }

        // ---- decoder heads ----
        if (t >= LL) {
            int td = t - LL;
            *reinterpret_cast<float2*>(hbuf + e * BT + c0) = make_float2(h0, h1);
            __syncthreads();                  // h complete for heads
            if (w < 8) {
                int r = w;                    // warps 0-7 -> 8 batch rows
                float hm = 0.f, hs = 0.f, hv0 = 0.f, hv1 = 0.f, hv2 = 0.f, hv3 = 0.f;
#pragma unroll
                for (int q4 = 0; q4 < 4; ++q4) {
                    int jj = lane + q4 * 32;
                    float hh = hbuf[jj * BT + r];
                    hm  = fmaf(hh, hw[jj], hm);
                    hs  = fmaf(hh, hw[128 + jj], hs);
                    hv0 = fmaf(hh, hw[256 + jj], hv0);
                    hv1 = fmaf(hh, hw[384 + jj], hv1);
                    hv2 = fmaf(hh, hw[512 + jj], hv2);
                    hv3 = fmaf(hh, hw[640 + jj], hv3);
                }
#pragma unroll
                for (int off = 16; off; off >>= 1) {
                    hm  += __shfl_xor_sync(0xffffffffu, hm,  off);
                    hs  += __shfl_xor_sync(0xffffffffu, hs,  off);
                    hv0 += __shfl_xor_sync(0xffffffffu, hv0, off);
                    hv1 += __shfl_xor_sync(0xffffffffu, hv1, off);
                    hv2 += __shfl_xor_sync(0xffffffffu, hv2, off);
                    hv3 += __shfl_xor_sync(0xffffffffu, hv3, off);
                }
                if (lane == 0) {
                    float mu = hm + hw[768];
                    float sp = hs + hw[769];
                    float stdv = fmaxf(sp, 0.0f) + log1pf(__expf(-fabsf(sp)));
                    int b = b0r + r;
                    out[b * DEC + td] = mu;
                    out[BB * DEC + b * DEC + td] = stdv;
                    float* vo = out + 2 * BB * DEC + (b * DEC + td) * 4;
                    vo[0] = hv0 + hw[770]; vo[1] = hv1 + hw[771];
                    vo[2] = hv2 + hw[772]; vo[3] = hv3 + hw[773];
                    nxt[r * XST + 17] = __float2half(mu);   // mu feedback -> x_prev
                }
            }
        }
    }
}

// ---------------- launch ----------------
extern "C" void kernel_launch(void* const* d_in, const int* in_sizes, int n_in,
                              void* d_out, int out_size) {
    const int*   cat_in   = (const int*)d_in[0];
    const float* cont_in  = (const float*)d_in[1];
    const float* X_in     = (const float*)d_in[2];
    const int*   cat_out  = (const int*)d_in[3];
    const float* cont_out = (const float*)d_in[4];
    const float* emb      = (const float*)d_in[5];
    const float* cw       = (const float*)d_in[6];
    const float* Wih_e    = (const float*)d_in[7];
    const float* Whh_e    = (const float*)d_in[8];
    const float* b_e      = (const float*)d_in[9];
    const float* Wih_d    = (const float*)d_in[10];
    const float* Whh_d    = (const float*)d_in[11];
    const float* b_d      = (const float*)d_in[12];
    const float* Wm       = (const float*)d_in[13];
    const float* bm       = (const float*)d_in[14];
    const float* Ws       = (const float*)d_in[15];
    const float* bs       = (const float*)d_in[16];
    const float* Wv       = (const float*)d_in[17];
    const float* bv       = (const float*)d_in[18];
    float* out = (float*)d_out;

    uint4 *pWhe, *pWhd;
    float *pfe, *pfd;
    cudaGetSymbolAddress((void**)&pWhe, g_Whf_e);
    cudaGetSymbolAddress((void**)&pWhd, g_Whf_d);
    cudaGetSymbolAddress((void**)&pfe,  g_fe);
    cudaGetSymbolAddress((void**)&pfd,  g_fd);

    prep_Wfrag<<<(NFRAG + 255) / 256, 256>>>(Wih_e, Whh_e, pWhe);
    prep_Wfrag<<<(NFRAG + 255) / 256, 256>>>(Wih_d, Whh_d, pWhd);
    size_t ne = (size_t)BB * LL * EINF;
    prep_fe<<<(unsigned)((ne + 255) / 256), 256>>>(cat_in, cont_in, X_in, emb, cw, pfe);
    prep_fd<<<(BB * DEC * 17 + 255) / 256, 256>>>(cat_out, cont_out, emb, cw, pfd);

    cudaFuncSetAttribute(model_kernel, cudaFuncAttributeMaxDynamicSharedMemorySize,
                         SMEM_TOTAL);
    model_kernel<<<NCTA, NTHR, SMEM_TOTAL>>>(b_e, b_d, Wm, bm, Ws, bs, Wv, bv, out);
}

// round 14
// speedup vs baseline: 1.4111x; 1.4111x over previous
#include <cuda_runtime.h>
#include <cuda_fp16.h>
#include <cstdint>
#include <math.h>

// Problem constants
#define BB   1024
#define LL   2048
#define DEC  64
#define HH   128
#define GG   512         // 4*H gate rows
#define EINF 18          // encoder input features (16 emb + cont*w + x)
#define NKT  10          // k-tiles of 16 (k 0..159; 146..159 zero pad)
#define BT   8           // batch rows per CTA (= mma N)
#define NCTA (BB/BT)     // 128
#define NTHR 512         // 16 warps -> 4 per SMSP
#define NW   16
#define XST  200         // xhT row stride in fp16
#define FPW  20          // W fragments per warp: 2 mtiles x 10 ktiles
#define NFRAG (NW * FPW * 32)   // 10240

// Within-tile k permutation: thread t4's 4 B-halfs {2t4,2t4+1,2t4+8,2t4+9}
// land contiguously at position 4*t4 -> one LDS.64 per k-tile, 2-phase floor.
__host__ __device__ __forceinline__ int kperm(int k) {
    int kt = k >> 4, k16 = k & 15;
    int j = k16 >> 1, r = k16 & 1;
    int pos = (j < 4) ? (4 * j + r) : (4 * (j - 4) + 2 + r);
    return kt * 16 + pos;
}

// ---------------- persistent device scratch ----------------
__device__ uint4 g_Whf_e[NFRAG];   // enc W fp16, mma-fragment order (rows permuted, i/f/o pre-scaled by 0.5)
__device__ uint4 g_Whf_d[NFRAG];   // dec
__device__ float g_fe[(size_t)BB * LL * EINF];
__device__ float g_fd[BB * DEC * 17];

// ---------------- smem byte layout ----------------
#define XH0_OFF   0                         // 3200 B : xh^T fp16 [8][200] buf 0
#define XH1_OFF   3200                      // 3200 B : buf 1
#define HBUF_OFF  6400                      // 4096 B : h fp32 [128][8] (decoder)
#define HW_OFF    10496                     // 3096 B : head weights/biases
#define SMEM_TOTAL 13592

// ---------------- mma wrapper ----------------
__device__ __forceinline__ void mma_f16(float* d, const uint4& a,
                                        uint32_t b0, uint32_t b1) {
    asm volatile(
        "mma.sync.aligned.m16n8k16.row.col.f32.f16.f16.f32 "
        "{%0,%1,%2,%3}, {%4,%5,%6,%7}, {%8,%9}, {%0,%1,%2,%3};"
        : "+f"(d[0]), "+f"(d[1]), "+f"(d[2]), "+f"(d[3])
        : "r"(a.x), "r"(a.y), "r"(a.z), "r"(a.w), "r"(b0), "r"(b1));
}

// ---------------- fast activations (HW tanh, fp32) ----------------
__device__ __forceinline__ float th(float x) {
    float y;
    asm("tanh.approx.f32 %0, %1;" : "=f"(y) : "f"(x));
    return y;
}
// input already pre-scaled by 0.5 via weights/bias: sigmoid(2x) = .5*th(x)+.5
__device__ __forceinline__ float sgp(float xh) {
    return fmaf(0.5f, th(xh), 0.5f);
}

// ---------------- prep kernels ----------------
__device__ __forceinline__ float getW(const float* Wih, const float* Whh,
                                      int R, int k) {
    if (k < 18)  return Wih[R * 18 + k];
    if (k < 146) return Whh[R * 128 + (k - 18)];
    return 0.0f;
}
__device__ __forceinline__ uint32_t packh2(float a, float b) {
    __half2 h = __floats2half2_rn(a, b);   // low = a
    return *reinterpret_cast<uint32_t*>(&h);
}

// Row permutation: warp w, mtile mt, mma row (g | g+8) -> gate (2*mt+s) of
// element e = w*8 + g, i.e. gate row R = (2*mt+s)*128 + e.
// Gates i (mt0,s0), f (mt0,s1), o (mt1,s1) pre-scaled by 0.5; g (mt1,s0) not.
__global__ void prep_Wfrag(const float* __restrict__ Wih,
                           const float* __restrict__ Whh,
                           uint4* __restrict__ w_out) {
    int idx = blockIdx.x * blockDim.x + threadIdx.x;
    if (idx >= NFRAG) return;
    int frag = idx >> 5, lane = idx & 31;
    int w = frag / FPW, rem = frag - w * FPW;
    int mt = rem / NKT, kt = rem - mt * NKT;
    int g = lane >> 2, t4 = lane & 3;
    int e = w * 8 + g;
    int R0 = (2 * mt + 0) * 128 + e;   // s=0
    int R1 = (2 * mt + 1) * 128 + e;   // s=1
    float s0 = (mt == 1) ? 1.0f : 0.5f;   // gate g unscaled, i scaled
    float s1 = 0.5f;                      // f and o scaled
    int kc = kt * 16 + 2 * t4;
    float v[8];
    v[0] = s0 * getW(Wih, Whh, R0, kc);     v[1] = s0 * getW(Wih, Whh, R0, kc + 1);
    v[2] = s1 * getW(Wih, Whh, R1, kc);     v[3] = s1 * getW(Wih, Whh, R1, kc + 1);
    v[4] = s0 * getW(Wih, Whh, R0, kc + 8); v[5] = s0 * getW(Wih, Whh, R0, kc + 9);
    v[6] = s1 * getW(Wih, Whh, R1, kc + 8); v[7] = s1 * getW(Wih, Whh, R1, kc + 9);
    w_out[idx] = make_uint4(packh2(v[0], v[1]), packh2(v[2], v[3]),
                            packh2(v[4], v[5]), packh2(v[6], v[7]));
}

__global__ void prep_fe(const int* __restrict__ cat, const float* __restrict__ cont,
                        const float* __restrict__ X, const float* __restrict__ emb,
                        const float* __restrict__ cw, float* __restrict__ out) {
    size_t idx = (size_t)blockIdx.x * blockDim.x + threadIdx.x;
    if (idx >= (size_t)BB * LL * EINF) return;
    size_t bl = idx / EINF;
    int j = (int)(idx - bl * EINF);
    float v;
    if (j < 16)       v = emb[cat[bl] * 16 + j];
    else if (j == 16) v = cont[bl] * cw[0];
    else              v = X[bl];
    out[idx] = v;
}

__global__ void prep_fd(const int* __restrict__ cat, const float* __restrict__ cont,
                        const float* __restrict__ emb, const float* __restrict__ cw,
                        float* __restrict__ out) {
    int idx = blockIdx.x * blockDim.x + threadIdx.x;
    if (idx >= BB * DEC * 17) return;
    int bl = idx / 17, j = idx - bl * 17;
    out[idx] = (j < 16) ? emb[cat[bl] * 16 + j] : cont[bl] * cw[0];
}

// ---------------- main persistent kernel ----------------
__global__ void __launch_bounds__(NTHR, 1)
model_kernel(const float* __restrict__ b_e, const float* __restrict__ b_d,
             const float* __restrict__ Wm, const float* __restrict__ bm,
             const float* __restrict__ Wsw, const float* __restrict__ bs,
             const float* __restrict__ Wv, const float* __restrict__ bv,
             float* __restrict__ out) {
    extern __shared__ char smem[];
    __half* xbuf[2] = { reinterpret_cast<__half*>(smem + XH0_OFF),
                        reinterpret_cast<__half*>(smem + XH1_OFF) };
    float*  hbuf = reinterpret_cast<float*>(smem + HBUF_OFF);
    float*  hw   = reinterpret_cast<float*>(smem + HW_OFF);

    const int tid = threadIdx.x;
    const int b0r = blockIdx.x * BT;
    const int w = tid >> 5, lane = tid & 31;
    const int g = lane >> 2, t4 = lane & 3;
    const int e  = w * 8 + g;             // this thread's cell element
    const int c0 = 2 * t4;                // this thread's 2 batch cols
    const int hpos = kperm(18 + e);       // permuted position of h element (const)

    // ---- load encoder W into registers (20 frags = 80 regs) ----
    uint4 Wh[FPW];
    {
        const uint4* src = g_Whf_e + (size_t)w * FPW * 32 + lane;
#pragma unroll
        for (int i = 0; i < FPW; ++i) Wh[i] = src[i * 32];
    }
    // biases for element e (i/f/o pre-scaled to match weights)
    float bi = 0.5f * b_e[e], bf = 0.5f * b_e[128 + e];
    float bg = b_e[256 + e],  bo = 0.5f * b_e[384 + e];

    // zero both xh buffers (h0 = 0; K padding stays 0 forever)
    for (int i = tid; i < (2 * BT * XST) / 2; i += NTHR)
        reinterpret_cast<uint32_t*>(xbuf[0])[i] = 0;

    // head weights
    if (tid < 128) {
        hw[tid]       = Wm[tid];
        hw[128 + tid] = Wsw[tid];
#pragma unroll
        for (int d = 0; d < 4; ++d) hw[256 + d * 128 + tid] = Wv[d * 128 + tid];
    }
    if (tid == 0) {
        hw[768] = bm[0]; hw[769] = bs[0];
        hw[770] = bv[0]; hw[771] = bv[1]; hw[772] = bv[2]; hw[773] = bv[3];
    }
    __syncthreads();
    // initial x features (t=0) -> buffer 0 (permuted positions)
    if (tid < BT * EINF) {
        int pr = tid / EINF, pk = tid - pr * EINF;
        xbuf[0][pr * XST + kperm(pk)] =
            __float2half(g_fe[(size_t)(b0r + pr) * (LL * EINF) + pk]);
    }

    float c[2] = {0.f, 0.f};   // states: (e,c0), (e,c0+1)

#pragma unroll 1
    for (int t = 0; t < LL + DEC; ++t) {
        if (t == LL) {
            const uint4* src = g_Whf_d + (size_t)w * FPW * 32 + lane;
#pragma unroll
            for (int i = 0; i < FPW; ++i) Wh[i] = src[i * 32];
            bi = 0.5f * b_d[e]; bf = 0.5f * b_d[128 + e];
            bg = b_d[256 + e];  bo = 0.5f * b_d[384 + e];
        }
        const __half* cur = xbuf[t & 1];
        __half*       nxt = xbuf[(t + 1) & 1];
        __syncthreads();                      // cur complete (h + features)

        // ---- ISSUE feature prefetch LDG early; MMA phase hides its latency ----
        float pf = 0.0f; bool havepf = false; int pr = 0, kpos = 0;
        if (t < LL - 1) {
            if (tid < BT * EINF) {
                havepf = true; pr = tid / EINF; int pk = tid - pr * EINF;
                kpos = kperm(pk);
                pf = g_fe[(size_t)(b0r + pr) * (LL * EINF) + (size_t)(t + 1) * EINF + pk];
            }
        } else if (t >= LL && t < LL + DEC - 1) {
            int td = t - LL;
            if (tid < BT * 17) {
                havepf = true; pr = tid / 17; int pk = tid - pr * 17;
                kpos = kperm(pk);
                pf = g_fd[((b0r + pr) * DEC + td) * 17 + pk];
            }
        }

        // ---- gate GEMM: one LDS.64 per k-tile (permuted layout) ----
        const __half* xp = cur + g * XST + 4 * t4;
        float dA[4], dB[4];                   // dA = {i,f}, dB = {g,o}
        dA[0] = bi; dA[1] = bi; dA[2] = bf; dA[3] = bf;
        dB[0] = bg; dB[1] = bg; dB[2] = bo; dB[3] = bo;
#pragma unroll
        for (int kt = 0; kt < NKT; ++kt) {
            uint2 bvv = *reinterpret_cast<const uint2*>(xp + kt * 16);
            mma_f16(dA, Wh[kt],       bvv.x, bvv.y);
            mma_f16(dB, Wh[NKT + kt], bvv.x, bvv.y);
        }

        // ---- LSTM cell: fully in registers, fp32 (2 states/thread) ----
        c[0] = sgp(dA[2]) * c[0] + sgp(dA[0]) * th(dB[0]);
        c[1] = sgp(dA[3]) * c[1] + sgp(dA[1]) * th(dB[1]);
        float h0 = sgp(dB[2]) * th(c[0]);
        float h1 = sgp(dB[3]) * th(c[1]);
        nxt[c0 * XST + hpos]       = __float2half(h0);
        nxt[(c0 + 1) * XST + hpos] = __float2half(h1);

        // ---- store prefetched features / seam copy ----
        if (havepf) {
            nxt[pr * XST + kpos] = __float2half(pf);
        } else if (t == LL - 1) {
            // decoder t0 reuses encoder's last features; permuted feature
            // region occupies positions 0..17, copy raw (layout-invariant)
            if (tid < BT * EINF) {
                int qr = tid / EINF, qk = tid - qr * EINF;
                nxt[qr * XST + qk] = cur[qr * XST + qk];
            }
        }

        // ---- decoder heads ----
        if (t >= LL) {
            int td = t - LL;
            *reinterpret_cast<float2*>(hbuf + e * BT + c0) = make_float2(h0, h1);
            __syncthreads();                  // h complete for heads
            if (w < 8) {
                int r = w;                    // warps 0-7 -> 8 batch rows
                float hm = 0.f, hs = 0.f, hv0 = 0.f, hv1 = 0.f, hv2 = 0.f, hv3 = 0.f;
#pragma unroll
                for (int q4 = 0; q4 < 4; ++q4) {
                    int jj = lane + q4 * 32;
                    float hh = hbuf[jj * BT + r];
                    hm  = fmaf(hh, hw[jj], hm);
                    hs  = fmaf(hh, hw[128 + jj], hs);
                    hv0 = fmaf(hh, hw[256 + jj], hv0);
                    hv1 = fmaf(hh, hw[384 + jj], hv1);
                    hv2 = fmaf(hh, hw[512 + jj], hv2);
                    hv3 = fmaf(hh, hw[640 + jj], hv3);
                }
#pragma unroll
                for (int off = 16; off; off >>= 1) {
                    hm  += __shfl_xor_sync(0xffffffffu, hm,  off);
                    hs  += __shfl_xor_sync(0xffffffffu, hs,  off);
                    hv0 += __shfl_xor_sync(0xffffffffu, hv0, off);
                    hv1 += __shfl_xor_sync(0xffffffffu, hv1, off);
                    hv2 += __shfl_xor_sync(0xffffffffu, hv2, off);
                    hv3 += __shfl_xor_sync(0xffffffffu, hv3, off);
                }
                if (lane == 0) {
                    float mu = hm + hw[768];
                    float sp = hs + hw[769];
                    float stdv = fmaxf(sp, 0.0f) + log1pf(__expf(-fabsf(sp)));
                    int b = b0r + r;
                    out[b * DEC + td] = mu;
                    out[BB * DEC + b * DEC + td] = stdv;
                    float* vo = out + 2 * BB * DEC + (b * DEC + td) * 4;
                    vo[0] = hv0 + hw[770]; vo[1] = hv1 + hw[771];
                    vo[2] = hv2 + hw[772]; vo[3] = hv3 + hw[773];
                    // mu feedback -> x_prev (logical k=17 -> permuted pos 17)
                    nxt[r * XST + 17] = __float2half(mu);
                }
            }
        }
    }
}

// ---------------- launch ----------------
extern "C" void kernel_launch(void* const* d_in, const int* in_sizes, int n_in,
                              void* d_out, int out_size) {
    const int*   cat_in   = (const int*)d_in[0];
    const float* cont_in  = (const float*)d_in[1];
    const float* X_in     = (const float*)d_in[2];
    const int*   cat_out  = (const int*)d_in[3];
    const float* cont_out = (const float*)d_in[4];
    const float* emb      = (const float*)d_in[5];
    const float* cw       = (const float*)d_in[6];
    const float* Wih_e    = (const float*)d_in[7];
    const float* Whh_e    = (const float*)d_in[8];
    const float* b_e      = (const float*)d_in[9];
    const float* Wih_d    = (const float*)d_in[10];
    const float* Whh_d    = (const float*)d_in[11];
    const float* b_d      = (const float*)d_in[12];
    const float* Wm       = (const float*)d_in[13];
    const float* bm       = (const float*)d_in[14];
    const float* Ws       = (const float*)d_in[15];
    const float* bs       = (const float*)d_in[16];
    const float* Wv       = (const float*)d_in[17];
    const float* bv       = (const float*)d_in[18];
    float* out = (float*)d_out;

    uint4 *pWhe, *pWhd;
    float *pfe, *pfd;
    cudaGetSymbolAddress((void**)&pWhe, g_Whf_e);
    cudaGetSymbolAddress((void**)&pWhd, g_Whf_d);
    cudaGetSymbolAddress((void**)&pfe,  g_fe);
    cudaGetSymbolAddress((void**)&pfd,  g_fd);

    prep_Wfrag<<<(NFRAG + 255) / 256, 256>>>(Wih_e, Whh_e, pWhe);
    prep_Wfrag<<<(NFRAG + 255) / 256, 256>>>(Wih_d, Whh_d, pWhd);
    size_t ne = (size_t)BB * LL * EINF;
    prep_fe<<<(unsigned)((ne + 255) / 256), 256>>>(cat_in, cont_in, X_in, emb, cw, pfe);
    prep_fd<<<(BB * DEC * 17 + 255) / 256, 256>>>(cat_out, cont_out, emb, cw, pfd);

    cudaFuncSetAttribute(model_kernel, cudaFuncAttributeMaxDynamicSharedMemorySize,
                         SMEM_TOTAL);
    model_kernel<<<NCTA, NTHR, SMEM_TOTAL>>>(b_e, b_d, Wm, bm, Ws, bs, Wv, bv, out);
}

// round 15
// speedup vs baseline: 1.5111x; 1.0709x over previous
#include <cuda_runtime.h>
#include <cuda_fp16.h>
#include <cstdint>
#include <math.h>

// Problem constants
#define BB   1024
#define LL   2048
#define DEC  64
#define HH   128
#define GG   512         // 4*H gate rows
#define EINF 18          // encoder input features (16 emb + cont*w + x)
#define NKT  10          // k-tiles of 16 (k 0..159; 146..159 zero pad)
#define BT   8           // batch rows per CTA (= mma N)
#define NCTA (BB/BT)     // 128
#define NTHR 512         // 16 warps -> 4 per SMSP
#define NW   16
#define XST  200         // xhT row stride in fp16
#define FPW  20          // W fragments per warp: 2 mtiles x 10 ktiles
#define NFRAG (NW * FPW * 32)   // 10240

// ---------------- persistent device scratch ----------------
__device__ uint4 g_Whf_e[NFRAG];   // enc W fp16, frag order, i/f/o pre-scaled 0.5
__device__ uint4 g_Whf_d[NFRAG];   // dec
__device__ float g_fe[(size_t)BB * LL * EINF];
__device__ float g_fd[BB * DEC * 17];

// ---------------- smem byte layout ----------------
#define XH0_OFF   0                         // 3200 B : xh^T fp16 [8][200] buf 0
#define XH1_OFF   3200                      // 3200 B : buf 1
#define HBUF_OFF  6400                      // 4096 B : h fp32 [128][8] (decoder)
#define HW_OFF    10496                     // 3096 B : head weights/biases
#define SMEM_TOTAL 13592

// ---------------- mma wrapper ----------------
__device__ __forceinline__ void mma_f16(float* d, const uint4& a,
                                        uint32_t b0, uint32_t b1) {
    asm volatile(
        "mma.sync.aligned.m16n8k16.row.col.f32.f16.f16.f32 "
        "{%0,%1,%2,%3}, {%4,%5,%6,%7}, {%8,%9}, {%0,%1,%2,%3};"
        : "+f"(d[0]), "+f"(d[1]), "+f"(d[2]), "+f"(d[3])
        : "r"(a.x), "r"(a.y), "r"(a.z), "r"(a.w), "r"(b0), "r"(b1));
}

// ---------------- fast activations (HW tanh, fp32) ----------------
__device__ __forceinline__ float th(float x) {
    float y;
    asm("tanh.approx.f32 %0, %1;" : "=f"(y) : "f"(x));
    return y;
}
// input pre-scaled by 0.5 via weights/bias: sigmoid(2x) = .5*th(x)+.5
__device__ __forceinline__ float sgp(float xh) {
    return fmaf(0.5f, th(xh), 0.5f);
}

// ---------------- merged prep (single kernel -> model_kernel is launch #2) ----
__device__ __forceinline__ float getW(const float* Wih, const float* Whh,
                                      int R, int k) {
    if (k < 18)  return Wih[R * 18 + k];
    if (k < 146) return Whh[R * 128 + (k - 18)];
    return 0.0f;
}
__device__ __forceinline__ uint32_t packh2(float a, float b) {
    __half2 h = __floats2half2_rn(a, b);   // low = a
    return *reinterpret_cast<uint32_t*>(&h);
}

#define WBLK  (NFRAG / 256)                         // 40
#define FEBLK ((int)(((size_t)BB * LL * EINF + 255) / 256))
#define FDBLK ((BB * DEC * 17 + 255) / 256)
#define PREP_GRID (2 * WBLK + FEBLK + FDBLK)

__device__ void prep_W_one(const float* __restrict__ Wih,
                           const float* __restrict__ Whh,
                           uint4* __restrict__ w_out, int idx) {
    int frag = idx >> 5, lane = idx & 31;
    int w = frag / FPW, rem = frag - w * FPW;
    int mt = rem / NKT, kt = rem - mt * NKT;
    int g = lane >> 2, t4 = lane & 3;
    int e = w * 8 + g;
    int R0 = (2 * mt + 0) * 128 + e;   // s=0
    int R1 = (2 * mt + 1) * 128 + e;   // s=1
    float s0 = (mt == 1) ? 1.0f : 0.5f;   // gate g unscaled; i scaled
    float s1 = 0.5f;                      // f and o scaled
    int kc = kt * 16 + 2 * t4;
    float v[8];
    v[0] = s0 * getW(Wih, Whh, R0, kc);     v[1] = s0 * getW(Wih, Whh, R0, kc + 1);
    v[2] = s1 * getW(Wih, Whh, R1, kc);     v[3] = s1 * getW(Wih, Whh, R1, kc + 1);
    v[4] = s0 * getW(Wih, Whh, R0, kc + 8); v[5] = s0 * getW(Wih, Whh, R0, kc + 9);
    v[6] = s1 * getW(Wih, Whh, R1, kc + 8); v[7] = s1 * getW(Wih, Whh, R1, kc + 9);
    w_out[idx] = make_uint4(packh2(v[0], v[1]), packh2(v[2], v[3]),
                            packh2(v[4], v[5]), packh2(v[6], v[7]));
}

__global__ void prep_all(const float* __restrict__ Wih_e, const float* __restrict__ Whh_e,
                         const float* __restrict__ Wih_d, const float* __restrict__ Whh_d,
                         const int* __restrict__ cat_in, const float* __restrict__ cont_in,
                         const float* __restrict__ X_in,
                         const int* __restrict__ cat_out, const float* __restrict__ cont_out,
                         const float* __restrict__ emb, const float* __restrict__ cw) {
    int blk = blockIdx.x;
    if (blk < WBLK) {
        prep_W_one(Wih_e, Whh_e, g_Whf_e, blk * 256 + threadIdx.x);
    } else if (blk < 2 * WBLK) {
        prep_W_one(Wih_d, Whh_d, g_Whf_d, (blk - WBLK) * 256 + threadIdx.x);
    } else if (blk < 2 * WBLK + FEBLK) {
        size_t idx = (size_t)(blk - 2 * WBLK) * 256 + threadIdx.x;
        if (idx < (size_t)BB * LL * EINF) {
            size_t bl = idx / EINF;
            int j = (int)(idx - bl * EINF);
            float v;
            if (j < 16)       v = emb[cat_in[bl] * 16 + j];
            else if (j == 16) v = cont_in[bl] * cw[0];
            else              v = X_in[bl];
            g_fe[idx] = v;
        }
    } else {
        int idx = (blk - 2 * WBLK - FEBLK) * 256 + threadIdx.x;
        if (idx < BB * DEC * 17) {
            int bl = idx / 17, j = idx - bl * 17;
            g_fd[idx] = (j < 16) ? emb[cat_out[bl] * 16 + j] : cont_out[bl] * cw[0];
        }
    }
}

// ---------------- main persistent kernel ----------------
__global__ void __launch_bounds__(NTHR, 1)
model_kernel(const float* __restrict__ b_e, const float* __restrict__ b_d,
             const float* __restrict__ Wm, const float* __restrict__ bm,
             const float* __restrict__ Wsw, const float* __restrict__ bs,
             const float* __restrict__ Wv, const float* __restrict__ bv,
             float* __restrict__ out) {
    extern __shared__ char smem[];
    __half* xbuf[2] = { reinterpret_cast<__half*>(smem + XH0_OFF),
                        reinterpret_cast<__half*>(smem + XH1_OFF) };
    float*  hbuf = reinterpret_cast<float*>(smem + HBUF_OFF);
    float*  hw   = reinterpret_cast<float*>(smem + HW_OFF);

    const int tid = threadIdx.x;
    const int b0r = blockIdx.x * BT;
    const int w = tid >> 5, lane = tid & 31;
    const int g = lane >> 2, t4 = lane & 3;
    const int e  = w * 8 + g;             // this thread's cell element
    const int c0 = 2 * t4;                // this thread's 2 batch cols

    // ---- load encoder W into registers (20 frags = 80 regs) ----
    uint4 Wh[FPW];
    {
        const uint4* src = g_Whf_e + (size_t)w * FPW * 32 + lane;
#pragma unroll
        for (int i = 0; i < FPW; ++i) Wh[i] = src[i * 32];
    }
    // biases for element e (i/f/o pre-scaled to match weights)
    float bi = 0.5f * b_e[e], bf = 0.5f * b_e[128 + e];
    float bg = b_e[256 + e],  bo = 0.5f * b_e[384 + e];

    // zero both xh buffers (h0 = 0; K padding stays 0 forever)
    for (int i = tid; i < (2 * BT * XST) / 2; i += NTHR)
        reinterpret_cast<uint32_t*>(xbuf[0])[i] = 0;

    // head weights
    if (tid < 128) {
        hw[tid]       = Wm[tid];
        hw[128 + tid] = Wsw[tid];
#pragma unroll
        for (int d = 0; d < 4; ++d) hw[256 + d * 128 + tid] = Wv[d * 128 + tid];
    }
    if (tid == 0) {
        hw[768] = bm[0]; hw[769] = bs[0];
        hw[770] = bv[0]; hw[771] = bv[1]; hw[772] = bv[2]; hw[773] = bv[3];
    }
    __syncthreads();
    // initial x features (t=0) -> buffer 0
    if (tid < BT * EINF) {
        int pr = tid / EINF, pk = tid - pr * EINF;
        xbuf[0][pr * XST + pk] =
            __float2half(g_fe[(size_t)(b0r + pr) * (LL * EINF) + pk]);
    }

    float c[2] = {0.f, 0.f};   // states: (e,c0), (e,c0+1)

#pragma unroll 1
    for (int t = 0; t < LL + DEC; ++t) {
        if (t == LL) {
            const uint4* src = g_Whf_d + (size_t)w * FPW * 32 + lane;
#pragma unroll
            for (int i = 0; i < FPW; ++i) Wh[i] = src[i * 32];
            bi = 0.5f * b_d[e]; bf = 0.5f * b_d[128 + e];
            bg = b_d[256 + e];  bo = 0.5f * b_d[384 + e];
        }
        const __half* cur = xbuf[t & 1];
        __half*       nxt = xbuf[(t + 1) & 1];
        __syncthreads();                      // cur complete (h + features)

        // ---- ISSUE feature prefetch LDG early; MMA phase hides its latency ----
        float pf = 0.0f; bool havepf = false; int pr = 0, pk = 0;
        if (t < LL - 1) {
            if (tid < BT * EINF) {
                havepf = true; pr = tid / EINF; pk = tid - pr * EINF;
                pf = g_fe[(size_t)(b0r + pr) * (LL * EINF) + (size_t)(t + 1) * EINF + pk];
            }
        } else if (t >= LL && t < LL + DEC - 1) {
            int td = t - LL;
            if (tid < BT * 17) {
                havepf = true; pr = tid / 17; pk = tid - pr * 17;
                pf = g_fd[((b0r + pr) * DEC + td) * 17 + pk];
            }
        }

        // ---- gate GEMM: B-frags loaded per k-tile ----
        const __half* xp = cur + g * XST;
        float dA[4], dB[4];                   // dA = {i,f}, dB = {g,o}
        dA[0] = bi; dA[1] = bi; dA[2] = bf; dA[3] = bf;
        dB[0] = bg; dB[1] = bg; dB[2] = bo; dB[3] = bo;
#pragma unroll
        for (int kt = 0; kt < NKT; ++kt) {
            uint32_t b0 = *reinterpret_cast<const uint32_t*>(xp + kt * 16 + 2 * t4);
            uint32_t b1 = *reinterpret_cast<const uint32_t*>(xp + kt * 16 + 2 * t4 + 8);
            mma_f16(dA, Wh[kt],       b0, b1);
            mma_f16(dB, Wh[NKT + kt], b0, b1);
        }

        // ---- LSTM cell: fully in registers, fp32 (2 states/thread) ----
        c[0] = sgp(dA[2]) * c[0] + sgp(dA[0]) * th(dB[0]);
        c[1] = sgp(dA[3]) * c[1] + sgp(dA[1]) * th(dB[1]);
        float h0 = sgp(dB[2]) * th(c[0]);
        float h1 = sgp(dB[3]) * th(c[1]);
        nxt[c0 * XST + 18 + e]       = __float2half(h0);
        nxt[(c0 + 1) * XST + 18 + e] = __float2half(h1);

        // ---- store prefetched features / seam copy ----
        if (havepf) {
            nxt[pr * XST + pk] = __float2half(pf);
        } else if (t == LL - 1) {
            // decoder t0 reuses encoder's last features (f_prev, x_prev)
            if (tid < BT * EINF) {
                int qr = tid / EINF, qk = tid - qr * EINF;
                nxt[qr * XST + qk] = cur[qr * XST + qk];
            }
        }

        // ---- decoder heads ----
        if (t >= LL) {
            int td = t - LL;
            *reinterpret_cast<float2*>(hbuf + e * BT + c0) = make_float2(h0, h1);
            __syncthreads();                  // h complete for heads
            if (w < 8) {
                int r = w;                    // warps 0-7 -> 8 batch rows
                float hm = 0.f, hs = 0.f, hv0 = 0.f, hv1 = 0.f, hv2 = 0.f, hv3 = 0.f;
#pragma unroll
                for (int q4 = 0; q4 < 4; ++q4) {
                    int jj = lane + q4 * 32;
                    float hh = hbuf[jj * BT + r];
                    hm  = fmaf(hh, hw[jj], hm);
                    hs  = fmaf(hh, hw[128 + jj], hs);
                    hv0 = fmaf(hh, hw[256 + jj], hv0);
                    hv1 = fmaf(hh, hw[384 + jj], hv1);
                    hv2 = fmaf(hh, hw[512 + jj], hv2);
                    hv3 = fmaf(hh, hw[640 + jj], hv3);
                }
#pragma unroll
                for (int off = 16; off; off >>= 1) {
                    hm  += __shfl_xor_sync(0xffffffffu, hm,  off);
                    hs  += __shfl_xor_sync(0xffffffffu, hs,  off);
                    hv0 += __shfl_xor_sync(0xffffffffu, hv0, off);
                    hv1 += __shfl_xor_sync(0xffffffffu, hv1, off);
                    hv2 += __shfl_xor_sync(0xffffffffu, hv2, off);
                    hv3 += __shfl_xor_sync(0xffffffffu, hv3, off);
                }
                if (lane == 0) {
                    float mu = hm + hw[768];
                    float sp = hs + hw[769];
                    float stdv = fmaxf(sp, 0.0f) + log1pf(__expf(-fabsf(sp)));
                    int b = b0r + r;
                    out[b * DEC + td] = mu;
                    out[BB * DEC + b * DEC + td] = stdv;
                    float* vo = out + 2 * BB * DEC + (b * DEC + td) * 4;
                    vo[0] = hv0 + hw[770]; vo[1] = hv1 + hw[771];
                    vo[2] = hv2 + hw[772]; vo[3] = hv3 + hw[773];
                    nxt[r * XST + 17] = __float2half(mu);   // mu feedback -> x_prev
                }
            }
        }
    }
}

// ---------------- launch ----------------
extern "C" void kernel_launch(void* const* d_in, const int* in_sizes, int n_in,
                              void* d_out, int out_size) {
    const int*   cat_in   = (const int*)d_in[0];
    const float* cont_in  = (const float*)d_in[1];
    const float* X_in     = (const float*)d_in[2];
    const int*   cat_out  = (const int*)d_in[3];
    const float* cont_out = (const float*)d_in[4];
    const float* emb      = (const float*)d_in[5];
    const float* cw       = (const float*)d_in[6];
    const float* Wih_e    = (const float*)d_in[7];
    const float* Whh_e    = (const float*)d_in[8];
    const float* b_e      = (const float*)d_in[9];
    const float* Wih_d    = (const float*)d_in[10];
    const float* Whh_d    = (const float*)d_in[11];
    const float* b_d      = (const float*)d_in[12];
    const float* Wm       = (const float*)d_in[13];
    const float* bm       = (const float*)d_in[14];
    const float* Ws       = (const float*)d_in[15];
    const float* bs       = (const float*)d_in[16];
    const float* Wv       = (const float*)d_in[17];
    const float* bv       = (const float*)d_in[18];
    float* out = (float*)d_out;

    // single prep launch -> model_kernel sits at even launch positions,
    // so ncu's "-s 5 -c 1" (skip 5, capture 6th) finally profiles it.
    prep_all<<<PREP_GRID, 256>>>(Wih_e, Whh_e, Wih_d, Whh_d,
                                 cat_in, cont_in, X_in, cat_out, cont_out,
                                 emb, cw);

    cudaFuncSetAttribute(model_kernel, cudaFuncAttributeMaxDynamicSharedMemorySize,
                         SMEM_TOTAL);
    model_kernel<<<NCTA, NTHR, SMEM_TOTAL>>>(b_e, b_d, Wm, bm, Ws, bs, Wv, bv, out);
}